// round 17
// baseline (speedup 1.0000x reference)
#include <cuda_runtime.h>
#include <cuda_bf16.h>
#include <stdint.h>

// ---------------- problem constants ----------------
#define NB   32
#define CIN  256
#define COUT 256
#define H    56
#define W    56
#define HW   (H*W)          // 3136
#define NHW  (NB*HW)        // 100352
#define CW   8              // 256 bits = 8 u32 words
#define TAPS 9

// persistent conv grid: 2 CTAs per SM on GB300 (152 SMs)
#define NSM      152
#define CONV_CTAS (2*NSM)   // 304
// item = (n, h, half-row of 28 px): 32*56*2 = 3584 items, 112 per batch
#define WHALF 28
#define IPB   (H*2)         // 112 items per batch
#define NITEMS (NB*IPB)     // 3584

// combined pack kernel grid split (pack_x handles 4 pixels/thread via float4)
#define XBLK4 ((NHW/4 + 255)/256)           // 98 blocks: pack_x
#define WBLK  ((COUT*TAPS*CW + 255)/256)    // 72 blocks: pack_w + zero stats

// ---------------- device scratch ----------------
__device__ uint32_t g_xb[(size_t)NB*HW*CW];   // packed activations [n][h][w][8] (3.2 MB)
__device__ uint32_t g_wb[COUT*TAPS*CW];       // packed weights [oc][tap][8] (72 KB)
__device__ short    g_y[(size_t)NHW*COUT];    // conv result NHWC int16 (51 MB)
__device__ int                g_sum[COUT];
__device__ unsigned long long g_sq[COUT];
__device__ float    g_scale[COUT];            // holds inv_std after conv
__device__ float    g_shift[COUT];            // holds mean after conv
__device__ int      g_done;                   // conv CTA completion counter

// ---------------- kernel 1: combined pack (x bitplanes x4 | w bitplanes + zero stats) ----------------
__global__ void pack_kernel(const float* __restrict__ x, const float* __restrict__ w) {
    if (blockIdx.x < XBLK4) {
        // ---- pack x: 4 consecutive pixels per thread (float4 loads) ----
        int t4 = blockIdx.x * 256 + threadIdx.x;       // one thread per 4 pixels
        if (t4 >= NHW / 4) return;
        int pix = t4 * 4;
        int n   = pix / HW;
        int rem = pix - n * HW;                        // multiple of 4 within [0,HW)

        uint32_t wds[4][CW];
#pragma unroll
        for (int j = 0; j < 4; j++)
#pragma unroll
            for (int i = 0; i < CW; i++) wds[j][i] = 0u;

        const float* xb = x + (size_t)n * CIN * HW + rem;
#pragma unroll 8
        for (int c = 0; c < CIN; c++) {
            float4 v = __ldg(reinterpret_cast<const float4*>(xb + (size_t)c * HW));
            uint32_t m = 1u << (c & 31);
            int wi = c >> 5;
            if (v.x > 0.f) wds[0][wi] |= m;
            if (v.y > 0.f) wds[1][wi] |= m;
            if (v.z > 0.f) wds[2][wi] |= m;
            if (v.w > 0.f) wds[3][wi] |= m;
        }
#pragma unroll
        for (int j = 0; j < 4; j++) {
            uint4* dst = reinterpret_cast<uint4*>(&g_xb[(size_t)(pix + j) * CW]);
            dst[0] = make_uint4(wds[j][0], wds[j][1], wds[j][2], wds[j][3]);
            dst[1] = make_uint4(wds[j][4], wds[j][5], wds[j][6], wds[j][7]);
        }
    } else {
        // ---- pack w + zero accumulators ----
        int tid = (blockIdx.x - XBLK4) * 256 + threadIdx.x;
        if (tid == 0) g_done = 0;
        if (tid < COUT) { g_sum[tid] = 0; g_sq[tid] = 0ull; }
        if (tid >= COUT * TAPS * CW) return;
        int oc   = tid / (TAPS * CW);
        int r    = tid - oc * (TAPS * CW);
        int tap  = r >> 3;
        int word = r & 7;

        uint32_t bits = 0u;
#pragma unroll
        for (int j = 0; j < 32; j++) {
            int ci = (word << 5) + j;
            float v = w[(size_t)(oc * CIN + ci) * TAPS + tap];
            bits |= (v > 0.f ? 1u : 0u) << j;
        }
        g_wb[tid] = bits;
    }
}

// ---------------- kernel 2: persistent XNOR-popcount conv (plain POPC) + fused BN stats ----------------
__global__ void __launch_bounds__(256, 2)
conv_kernel() {
    __shared__ uint32_t sx[3][WHALF + 2][CW];          // 2.9 KB per CTA
    __shared__ int islast;

    const int oc = threadIdx.x;

    // per-thread weights (72 regs) + per-tap zero-halo correction Ct
    uint32_t wr[TAPS][CW];
    int      Ct[TAPS];
    {
        const uint32_t* wp = &g_wb[(size_t)oc * TAPS * CW];
#pragma unroll
        for (int t = 0; t < TAPS; t++) {
            int p = 0;
#pragma unroll
            for (int k = 0; k < CW; k++) {
                uint32_t v = __ldg(wp + t * CW + k);
                wr[t][k] = v;
                p += __popc(v);
            }
            Ct[t] = CIN - 2 * p;                       // contribution of a zero-halo tap
        }
    }

    int       lsum = 0;
    long long lsq  = 0;

    for (int item = blockIdx.x; item < NITEMS; item += CONV_CTAS) {
        const int n   = item / IPB;                    // 112 items per batch
        const int r2  = item - n * IPB;                // h*2 + whalf
        const int h   = r2 >> 1;
        const int wh0 = (r2 & 1) * WHALF;

        __syncthreads();                               // protect prior sx reads

        // cooperative load of x bit-tile: rows h-1..h+1, cols wh0-1..wh0+28
        const int TOT = 3 * (WHALF + 2) * CW;          // 720 words
        for (int i = oc; i < TOT; i += 256) {
            int wrd  = i & 7;
            int rest = i >> 3;
            int lc   = rest % (WHALF + 2);
            int r    = rest / (WHALF + 2);
            int gh   = h - 1 + r;
            int gw   = wh0 - 1 + lc;
            uint32_t v = 0u;
            if (gh >= 0 && gh < H && gw >= 0 && gw < W)
                v = g_xb[(((size_t)n * H + gh) * W + gw) * CW + wrd];
            sx[r][lc][wrd] = v;
        }
        __syncthreads();

        // per-item uniform h-border correction (subtracted from every pixel)
        const int invH = (h == 0 ? 0x007 : 0) | (h == H - 1 ? 0x1C0 : 0);
        int cH = 0;
        if (invH) {
#pragma unroll
            for (int t = 0; t < TAPS; t++)
                if ((invH >> t) & 1) cH += Ct[t];
        }

        short* yrow = &g_y[(((size_t)n * H + h) * W + wh0) * COUT + oc];
        int isum = 0;                                  // per-item int32 stats
        int isq  = 0;                                  // max 28*2304^2 = 1.49e8 < 2^31

        for (int ol = 0; ol < WHALF; ol++) {
            // 4 independent accumulators: ILP for the popc-add chain
            int s0 = 0, sA = 0, s2 = 0, s3 = 0;
#pragma unroll
            for (int t = 0; t < TAPS; t++) {
                const int r = t / 3;
                const int c = ol + t % 3;
                const uint4 xa = *reinterpret_cast<const uint4*>(&sx[r][c][0]);
                const uint4 xb = *reinterpret_cast<const uint4*>(&sx[r][c][4]);
                s0 += __popc(xa.x ^ wr[t][0]);
                sA += __popc(xa.y ^ wr[t][1]);
                s2 += __popc(xa.z ^ wr[t][2]);
                s3 += __popc(xa.w ^ wr[t][3]);
                s0 += __popc(xb.x ^ wr[t][4]);
                sA += __popc(xb.y ^ wr[t][5]);
                s2 += __popc(xb.z ^ wr[t][6]);
                s3 += __popc(xb.w ^ wr[t][7]);
            }
            int s  = (s0 + sA) + (s2 + s3);            // exact Σ popc over 72 words
            int yv = CIN * TAPS - 2 * s - cH;          // h-border corrected (uniform)

            // rare w-border pixels: fully recompute correction (warp-uniform branch)
            if ((wh0 == 0 && ol == 0) || (wh0 == WHALF && ol == WHALF - 1)) {
                int inv = invH | (ol == 0 ? 0x049 : 0x124);
                yv = CIN * TAPS - 2 * s;
#pragma unroll
                for (int t = 0; t < TAPS; t++)
                    if ((inv >> t) & 1) yv -= Ct[t];
            }

            yrow[(size_t)ol * COUT] = (short)yv;       // NHWC: coalesced over oc
            isum += yv;
            isq  += yv * yv;
        }
        lsum += isum;
        lsq  += (long long)isq;
    }

    atomicAdd(&g_sum[oc], lsum);
    atomicAdd(&g_sq[oc], (unsigned long long)lsq);
    __threadfence();

    // ---- last CTA computes inv_std/mean (fused stats) ----
    if (threadIdx.x == 0)
        islast = (atomicAdd(&g_done, 1) == CONV_CTAS - 1);
    __syncthreads();
    if (islast) {
        int c = oc;
        int                s = atomicAdd(&g_sum[c], 0);             // L2-coherent read
        unsigned long long q = atomicAdd(&g_sq[c], 0ull);
        const double cnt  = (double)NHW;
        double mean = (double)s / cnt;
        double ex2  = (double)(long long)q / cnt;
        double var  = ex2 - mean * mean;
        double inv  = 1.0 / sqrt(var + 1e-5);
        g_scale[c] = (float)inv;                                    // inv_std
        g_shift[c] = (float)mean;                                   // mean
    }
}

// ---------------- kernel 3: BN apply (folds gamma/beta) + NHWC -> NCHW ----------------
#define WT 28
__global__ void __launch_bounds__(256)
apply_kernel(float* __restrict__ out,
             const float* __restrict__ gamma,
             const float* __restrict__ beta) {
    __shared__ float sy[WT * 257];                     // padded: conflict-free both phases
    __shared__ float ssc[COUT], ssh[COUT];
    const int wt = blockIdx.x, h = blockIdx.y, n = blockIdx.z;
    const int tid = threadIdx.x;

    {   // fold gamma/beta with (inv_std, mean) once per CTA
        float inv  = g_scale[tid];
        float mean = g_shift[tid];
        float sc   = gamma[tid] * inv;
        ssc[tid] = sc;
        ssh[tid] = beta[tid] - mean * sc;
    }
    __syncthreads();

    for (int idx = tid; idx < WT * COUT; idx += 256) {
        int lw = idx >> 8;
        int oc = idx & 255;
        int gw = wt * WT + lw;
        float yv = (float)g_y[(((size_t)n * H + h) * W + gw) * COUT + oc];
        sy[lw * 257 + oc] = yv * ssc[oc] + ssh[oc];
    }
    __syncthreads();
    for (int idx = tid; idx < WT * COUT; idx += 256) {
        int oc = idx / WT;
        int lw = idx - oc * WT;
        out[(((size_t)n * COUT + oc) * H + h) * W + wt * WT + lw] = sy[lw * 257 + oc];
    }
}

// ---------------- launch ----------------
extern "C" void kernel_launch(void* const* d_in, const int* in_sizes, int n_in,
                              void* d_out, int out_size) {
    const float* x     = (const float*)d_in[0];
    const float* w     = (const float*)d_in[1];
    const float* gamma = (const float*)d_in[2];
    const float* beta  = (const float*)d_in[3];
    float* out = (float*)d_out;

    pack_kernel<<<XBLK4 + WBLK, 256>>>(x, w);
    conv_kernel<<<CONV_CTAS, 256>>>();
    apply_kernel<<<dim3(W / WT, H, NB), 256>>>(out, gamma, beta);
}